// round 1
// baseline (speedup 1.0000x reference)
#include <cuda_runtime.h>
#include <cuda_bf16.h>
#include <math.h>

// ---------------------------------------------------------------------------
// fkopt_net: x[16384,3] -> MLP(1024,1024,1024,256) -> 64-joint quaternion FK
// Round 0: fp32 SIMT baseline.
//   L1: trivial K=3 kernel (leaky_relu)
//   L2/L3: 128x128x8 SMEM SGEMM, 8x8 register tile, fused bias+leaky_relu
//   L4: same GEMM, fused bias+tanh
//   FK: 1 thread/row, 3x3 rot + trans chain (w stays exactly 1.0)
// ---------------------------------------------------------------------------

#define BATCH 16384
#define H1    1024
#define H4    256
#define NEG_SLOPE 0.01f

// Scratch (allocation-free rule: __device__ globals)
__device__ float g_bufA[BATCH * H1];   // h1, then h3
__device__ float g_bufB[BATCH * H1];   // h2
__device__ float g_joints[BATCH * H4]; // tanh output

// ---------------------------------------------------------------------------
// Layer 1: out[m,n] = leaky( x[m,0]*W1[0,n] + x[m,1]*W1[1,n] + x[m,2]*W1[2,n] + b1[n] )
// ---------------------------------------------------------------------------
__global__ __launch_bounds__(256) void layer1_kernel(
    const float* __restrict__ x, const float* __restrict__ W1,
    const float* __restrict__ b1, float* __restrict__ out)
{
    int idx = blockIdx.x * blockDim.x + threadIdx.x;   // 0 .. BATCH*1024-1
    int m = idx >> 10;
    int n = idx & 1023;
    float x0 = __ldg(&x[m * 3 + 0]);
    float x1 = __ldg(&x[m * 3 + 1]);
    float x2 = __ldg(&x[m * 3 + 2]);
    float v = __ldg(&b1[n]);
    v = fmaf(x0, __ldg(&W1[0 * 1024 + n]), v);
    v = fmaf(x1, __ldg(&W1[1 * 1024 + n]), v);
    v = fmaf(x2, __ldg(&W1[2 * 1024 + n]), v);
    out[idx] = (v >= 0.0f) ? v : NEG_SLOPE * v;
}

// ---------------------------------------------------------------------------
// SGEMM: C[M,N] = act(A[M,K] @ B[K,N] + bias[N])
// BM=BN=128, BK=8, 256 threads, 8x8 per-thread tile.
// ACT: 0 = leaky_relu, 1 = tanh
// M,N,K all multiples of the tile sizes here (16384 / 1024|256 / 1024).
// ---------------------------------------------------------------------------
template <int ACT>
__global__ __launch_bounds__(256) void sgemm_act_kernel(
    const float* __restrict__ A, const float* __restrict__ B,
    const float* __restrict__ bias, float* __restrict__ C,
    int M, int N, int K)
{
    constexpr int BM = 128, BN = 128, BK = 8, TM = 8, TN = 8;
    __shared__ float As[BK][BM];      // transposed A tile
    __shared__ float Bs[BK][BN];

    const int tid = threadIdx.x;          // 0..255
    const int tx = tid & 15;              // 16 threads across N
    const int ty = tid >> 4;              // 16 threads across M

    // Global load mapping
    const int aRow  = tid >> 1;           // 0..127
    const int aCol4 = (tid & 1) * 4;      // 0 or 4
    const int bRow  = tid >> 5;           // 0..7
    const int bCol4 = (tid & 31) * 4;     // 0..124

    const float* Ab = A + (blockIdx.y * BM) * K;
    const float* Bb = B + blockIdx.x * BN;

    float acc[TM][TN];
    #pragma unroll
    for (int i = 0; i < TM; i++)
        #pragma unroll
        for (int j = 0; j < TN; j++) acc[i][j] = 0.0f;

    float aReg[TM], bReg[TN];

    for (int k0 = 0; k0 < K; k0 += BK) {
        float4 av = *(const float4*)(Ab + aRow * K + k0 + aCol4);
        As[aCol4 + 0][aRow] = av.x;
        As[aCol4 + 1][aRow] = av.y;
        As[aCol4 + 2][aRow] = av.z;
        As[aCol4 + 3][aRow] = av.w;
        *(float4*)&Bs[bRow][bCol4] =
            *(const float4*)(Bb + (k0 + bRow) * N + bCol4);
        __syncthreads();

        #pragma unroll
        for (int k = 0; k < BK; k++) {
            #pragma unroll
            for (int i = 0; i < TM; i++) aReg[i] = As[k][ty * TM + i];
            #pragma unroll
            for (int j = 0; j < TN; j++) bReg[j] = Bs[k][tx * TN + j];
            #pragma unroll
            for (int i = 0; i < TM; i++)
                #pragma unroll
                for (int j = 0; j < TN; j++)
                    acc[i][j] = fmaf(aReg[i], bReg[j], acc[i][j]);
        }
        __syncthreads();
    }

    // Epilogue: bias + activation, vectorized stores
    const int cRow0 = blockIdx.y * BM + ty * TM;
    const int cCol0 = blockIdx.x * BN + tx * TN;
    float bv[TN];
    #pragma unroll
    for (int j = 0; j < TN; j++) bv[j] = __ldg(&bias[cCol0 + j]);

    #pragma unroll
    for (int i = 0; i < TM; i++) {
        #pragma unroll
        for (int j = 0; j < TN; j += 4) {
            float4 v;
            v.x = acc[i][j + 0] + bv[j + 0];
            v.y = acc[i][j + 1] + bv[j + 1];
            v.z = acc[i][j + 2] + bv[j + 2];
            v.w = acc[i][j + 3] + bv[j + 3];
            if (ACT == 0) {
                v.x = (v.x >= 0.0f) ? v.x : NEG_SLOPE * v.x;
                v.y = (v.y >= 0.0f) ? v.y : NEG_SLOPE * v.y;
                v.z = (v.z >= 0.0f) ? v.z : NEG_SLOPE * v.z;
                v.w = (v.w >= 0.0f) ? v.w : NEG_SLOPE * v.w;
            } else {
                v.x = tanhf(v.x);
                v.y = tanhf(v.y);
                v.z = tanhf(v.z);
                v.w = tanhf(v.w);
            }
            *(float4*)(C + (cRow0 + i) * N + cCol0 + j) = v;
        }
    }
}

// ---------------------------------------------------------------------------
// FK chain: per row, 64 joints.
//   q = (w,x,y,z); s = 2/|q|^2; R = rotation; coordi translation = R[:,1]
//   cur.rot = prev.rot @ R ; cur.trans = prev.rot @ R[:,1] + prev.trans
//   bottom-right w stays exactly 1.0; out = trans / (1 + 1e-9) == trans (fp32)
// ---------------------------------------------------------------------------
__global__ __launch_bounds__(256) void fk_kernel(
    const float* __restrict__ joints, float* __restrict__ out)
{
    int row = blockIdx.x * blockDim.x + threadIdx.x;
    if (row >= BATCH) return;

    const float4* jq = (const float4*)(joints + row * 256);
    float* o = out + row * 192;

    // prev rotation = I, translation = 0
    float r00 = 1, r01 = 0, r02 = 0;
    float r10 = 0, r11 = 1, r12 = 0;
    float r20 = 0, r21 = 0, r22 = 1;
    float t0 = 0, t1 = 0, t2 = 0;

    #pragma unroll 4
    for (int j = 0; j < 64; j++) {
        float4 q = jq[j];
        float w = q.x, x = q.y, y = q.z, z = q.w;
        float s = 2.0f / (w * w + x * x + y * y + z * z);

        float R00 = 1.0f - s * (y * y + z * z);
        float R01 = s * (x * y - z * w);
        float R02 = s * (x * z + y * w);
        float R10 = s * (x * y + z * w);
        float R11 = 1.0f - s * (x * x + z * z);
        float R12 = s * (y * z - x * w);
        float R20 = s * (x * z - y * w);
        float R21 = s * (y * z + x * w);
        float R22 = 1.0f - s * (x * x + y * y);

        // new rot = prev.rot @ R
        float n00 = r00 * R00 + r01 * R10 + r02 * R20;
        float n01 = r00 * R01 + r01 * R11 + r02 * R21;
        float n02 = r00 * R02 + r01 * R12 + r02 * R22;
        float n10 = r10 * R00 + r11 * R10 + r12 * R20;
        float n11 = r10 * R01 + r11 * R11 + r12 * R21;
        float n12 = r10 * R02 + r11 * R12 + r12 * R22;
        float n20 = r20 * R00 + r21 * R10 + r22 * R20;
        float n21 = r20 * R01 + r21 * R11 + r22 * R21;
        float n22 = r20 * R02 + r21 * R12 + r22 * R22;

        // new trans = prev.rot @ R[:,1] + prev.trans
        float nt0 = r00 * R01 + r01 * R11 + r02 * R21 + t0;
        float nt1 = r10 * R01 + r11 * R11 + r12 * R21 + t1;
        float nt2 = r20 * R01 + r21 * R11 + r22 * R21 + t2;

        r00 = n00; r01 = n01; r02 = n02;
        r10 = n10; r11 = n11; r12 = n12;
        r20 = n20; r21 = n21; r22 = n22;
        t0 = nt0; t1 = nt1; t2 = nt2;

        o[j * 3 + 0] = t0;   // /(1+1e-9) is identity in fp32 (w == 1.0f exactly)
        o[j * 3 + 1] = t1;
        o[j * 3 + 2] = t2;
    }
}

// ---------------------------------------------------------------------------
// Launch
// ---------------------------------------------------------------------------
extern "C" void kernel_launch(void* const* d_in, const int* in_sizes, int n_in,
                              void* d_out, int out_size)
{
    const float* x  = (const float*)d_in[0];
    const float* W1 = (const float*)d_in[1];
    const float* b1 = (const float*)d_in[2];
    const float* W2 = (const float*)d_in[3];
    const float* b2 = (const float*)d_in[4];
    const float* W3 = (const float*)d_in[5];
    const float* b3 = (const float*)d_in[6];
    const float* W4 = (const float*)d_in[7];
    const float* b4 = (const float*)d_in[8];
    float* out = (float*)d_out;

    float* hA;
    float* hB;
    float* jnt;
    cudaGetSymbolAddress((void**)&hA,  g_bufA);
    cudaGetSymbolAddress((void**)&hB,  g_bufB);
    cudaGetSymbolAddress((void**)&jnt, g_joints);

    // L1: x[16384,3] @ W1[3,1024] -> hA
    layer1_kernel<<<(BATCH * H1) / 256, 256>>>(x, W1, b1, hA);

    // L2: hA @ W2[1024,1024] -> hB   (leaky)
    {
        dim3 grid(H1 / 128, BATCH / 128);
        sgemm_act_kernel<0><<<grid, 256>>>(hA, W2, b2, hB, BATCH, H1, H1);
    }
    // L3: hB @ W3[1024,1024] -> hA   (leaky)
    {
        dim3 grid(H1 / 128, BATCH / 128);
        sgemm_act_kernel<0><<<grid, 256>>>(hB, W3, b3, hA, BATCH, H1, H1);
    }
    // L4: hA @ W4[1024,256] -> joints   (tanh)
    {
        dim3 grid(H4 / 128, BATCH / 128);
        sgemm_act_kernel<1><<<grid, 256>>>(hA, W4, b4, jnt, BATCH, H4, H1);
    }
    // FK chain
    fk_kernel<<<BATCH / 256, 256>>>(jnt, out);
}

// round 3
// speedup vs baseline: 2.8125x; 2.8125x over previous
#include <cuda_runtime.h>
#include <cuda_fp16.h>
#include <math.h>
#include <stdint.h>

// ---------------------------------------------------------------------------
// fkopt_net round 3: mma.sync (HMMA) fp16x3-split GEMM pipeline.
//  Target is plain sm_100 (no tcgen05). Tensor work via mma.sync.m16n8k16.
//  A = Ah + Al (fp16 hi/lo), B likewise; D = AhBh + AlBh + AhBl in fp32.
//  All GEMM operands stored pre-tiled (8KB = 128 rows x 32 fp16) and
//  XOR-swizzled in global memory; stage loads are cp.async.bulk + mbarrier.
// ---------------------------------------------------------------------------

#define BATCH 16384
#define KDIM  1024
#define NEG_SLOPE 0.01f

// ---------------- scratch (device globals; no allocations) -----------------
__device__ __align__(1024) __half g_a0h[BATCH * KDIM];
__device__ __align__(1024) __half g_a0l[BATCH * KDIM];
__device__ __align__(1024) __half g_a1h[BATCH * KDIM];
__device__ __align__(1024) __half g_a1l[BATCH * KDIM];
__device__ __align__(1024) __half g_w2h[KDIM * KDIM];
__device__ __align__(1024) __half g_w2l[KDIM * KDIM];
__device__ __align__(1024) __half g_w3h[KDIM * KDIM];
__device__ __align__(1024) __half g_w3l[KDIM * KDIM];
__device__ __align__(1024) __half g_w4h[256 * KDIM];
__device__ __align__(1024) __half g_w4l[256 * KDIM];
__device__ __align__(1024) float g_joints[BATCH * 256];

// ---------------- PTX helpers ----------------------------------------------
__device__ __forceinline__ uint32_t smem_u32(const void* p) {
    uint32_t a;
    asm("{ .reg .u64 t; cvta.to.shared.u64 t, %1; cvt.u32.u64 %0, t; }"
        : "=r"(a) : "l"(p));
    return a;
}
__device__ __forceinline__ void mbar_init(uint32_t a, uint32_t c) {
    asm volatile("mbarrier.init.shared.b64 [%0], %1;" :: "r"(a), "r"(c) : "memory");
}
__device__ __forceinline__ void mbar_expect(uint32_t a, uint32_t tx) {
    asm volatile("mbarrier.arrive.expect_tx.shared.b64 _, [%0], %1;"
                 :: "r"(a), "r"(tx) : "memory");
}
__device__ __forceinline__ void mbar_wait(uint32_t a, uint32_t ph) {
    asm volatile(
        "{\n\t.reg .pred P;\n\t"
        "WL_%=:\n\t"
        "mbarrier.try_wait.parity.acquire.cta.shared::cta.b64 P, [%0], %1, 0x989680;\n\t"
        "@P bra.uni WD_%=;\n\t"
        "bra.uni WL_%=;\n\t"
        "WD_%=:\n\t}"
        :: "r"(a), "r"(ph) : "memory");
}
__device__ __forceinline__ void bulk_g2s(uint32_t dst, const void* src,
                                         uint32_t bytes, uint32_t mbar) {
    asm volatile(
        "cp.async.bulk.shared::cluster.global.mbarrier::complete_tx::bytes "
        "[%0], [%1], %2, [%3];"
        :: "r"(dst), "l"(src), "r"(bytes), "r"(mbar) : "memory");
}

#define LDSM4(r, a)                                                              \
    asm volatile("ldmatrix.sync.aligned.m8n8.x4.shared.b16 {%0,%1,%2,%3}, [%4];" \
                 : "=r"((r)[0]), "=r"((r)[1]), "=r"((r)[2]), "=r"((r)[3])        \
                 : "r"(a))
#define LDSM2(r, a)                                                              \
    asm volatile("ldmatrix.sync.aligned.m8n8.x2.shared.b16 {%0,%1}, [%2];"       \
                 : "=r"((r)[0]), "=r"((r)[1]) : "r"(a))
#define MMA16816(d, a, b)                                                        \
    asm volatile("mma.sync.aligned.m16n8k16.row.col.f32.f16.f16.f32 "            \
                 "{%0,%1,%2,%3}, {%4,%5,%6,%7}, {%8,%9}, {%0,%1,%2,%3};"         \
                 : "+f"((d)[0]), "+f"((d)[1]), "+f"((d)[2]), "+f"((d)[3])        \
                 : "r"((a)[0]), "r"((a)[1]), "r"((a)[2]), "r"((a)[3]),           \
                   "r"((b)[0]), "r"((b)[1]))

// tile byte-offset swizzle: off = row*64 + col*2 (32 fp16 cols per row)
__device__ __forceinline__ uint32_t swz(uint32_t off) {
    return off ^ (((off >> 7) & 3u) << 4);
}
__device__ __forceinline__ void split_h(float v, __half& h, __half& l) {
    h = __float2half_rn(v);
    l = __float2half_rn(v - __half2float(h));
}
__device__ __forceinline__ uint32_t pack_h2(__half a, __half b) {
    return ((uint32_t)__half_as_ushort(b) << 16) | (uint32_t)__half_as_ushort(a);
}

// ---------------------------------------------------------------------------
// Layer 1: x[16384,3] @ W1[3,1024] + b1, leaky -> tiled fp16 hi/lo
// One thread: one m row, 8 consecutive n.
// ---------------------------------------------------------------------------
__global__ __launch_bounds__(256) void layer1_kernel(
    const float* __restrict__ x, const float* __restrict__ W1,
    const float* __restrict__ b1,
    __half* __restrict__ Ohi, __half* __restrict__ Olo)
{
    int idx = blockIdx.x * 256 + threadIdx.x;   // BATCH*128 total
    int n0 = (idx & 127) * 8;
    int m  = idx >> 7;
    float x0 = __ldg(x + m * 3 + 0);
    float x1 = __ldg(x + m * 3 + 1);
    float x2 = __ldg(x + m * 3 + 2);

    uint32_t hw[4], lw[4];
    #pragma unroll
    for (int p = 0; p < 4; p++) {
        int n = n0 + 2 * p;
        float v0 = __ldg(b1 + n) + x0 * __ldg(W1 + n) +
                   x1 * __ldg(W1 + 1024 + n) + x2 * __ldg(W1 + 2048 + n);
        float v1 = __ldg(b1 + n + 1) + x0 * __ldg(W1 + n + 1) +
                   x1 * __ldg(W1 + 1024 + n + 1) + x2 * __ldg(W1 + 2048 + n + 1);
        v0 = (v0 >= 0.0f) ? v0 : NEG_SLOPE * v0;
        v1 = (v1 >= 0.0f) ? v1 : NEG_SLOPE * v1;
        __half h0, l0, h1, l1;
        split_h(v0, h0, l0); split_h(v1, h1, l1);
        hw[p] = pack_h2(h0, h1);
        lw[p] = pack_h2(l0, l1);
    }
    size_t tile = (size_t)(m >> 7) * 32 + (n0 >> 5);
    uint32_t off = swz((uint32_t)(m & 127) * 64 + (uint32_t)(n0 & 31) * 2);
    *(uint4*)((char*)Ohi + tile * 8192 + off) = make_uint4(hw[0], hw[1], hw[2], hw[3]);
    *(uint4*)((char*)Olo + tile * 8192 + off) = make_uint4(lw[0], lw[1], lw[2], lw[3]);
}

// ---------------------------------------------------------------------------
// Weight convert+transpose: W[K=1024, N] fp32 -> tiled fp16 hi/lo of W^T [N,K]
// One thread: one n, 8 consecutive k.
// ---------------------------------------------------------------------------
__global__ __launch_bounds__(256) void wconv_kernel(
    const float* __restrict__ W,
    __half* __restrict__ Ohi, __half* __restrict__ Olo, int N)
{
    int idx = blockIdx.x * 256 + threadIdx.x;   // N*128 total
    int n  = idx % N;
    int k0 = (idx / N) * 8;
    uint32_t hw[4], lw[4];
    #pragma unroll
    for (int p = 0; p < 4; p++) {
        float v0 = __ldg(W + (size_t)(k0 + 2 * p) * N + n);
        float v1 = __ldg(W + (size_t)(k0 + 2 * p + 1) * N + n);
        __half h0, l0, h1, l1;
        split_h(v0, h0, l0); split_h(v1, h1, l1);
        hw[p] = pack_h2(h0, h1);
        lw[p] = pack_h2(l0, l1);
    }
    size_t tile = (size_t)(n >> 7) * 32 + (k0 >> 5);
    uint32_t off = swz((uint32_t)(n & 127) * 64 + (uint32_t)(k0 & 31) * 2);
    *(uint4*)((char*)Ohi + tile * 8192 + off) = make_uint4(hw[0], hw[1], hw[2], hw[3]);
    *(uint4*)((char*)Olo + tile * 8192 + off) = make_uint4(lw[0], lw[1], lw[2], lw[3]);
}

// ---------------------------------------------------------------------------
// GEMM: C[16384, N] = act(A @ W + bias), fp16x3 mma.sync.
// CTA tile 128x128, BK=32, 4-stage cp.async.bulk pipeline.
// 8 warps, warp tile 64x32. MODE 0: leaky + tiled fp16 hi/lo out.
// MODE 1: tanh + fp32 row-major out (N=256).
// ---------------------------------------------------------------------------
template <int MODE>
__global__ __launch_bounds__(256, 1) void gemm_kernel(
    const __half* __restrict__ Ahg, const __half* __restrict__ Alg,
    const __half* __restrict__ Bhg, const __half* __restrict__ Blg,
    const float* __restrict__ bias,
    __half* __restrict__ Ohi, __half* __restrict__ Olo,
    float* __restrict__ Of, int Ntot)
{
    constexpr int NC = 32;                  // K=1024 / BK=32
    constexpr uint32_t STAGE = 32768;       // Ah,Al,Bh,Bl 8KB each
    __shared__ __align__(8) uint64_t bar_full[4];
    extern __shared__ char dsm[];
    const uint32_t sbase = (smem_u32(dsm) + 1023) & ~1023u;

    const int tid = threadIdx.x, lane = tid & 31, wid = tid >> 5;
    const int mb = blockIdx.y, nb = blockIdx.x;
    const int wm = (wid & 1) * 64;          // warp m offset in tile
    const int wn = (wid >> 1) * 32;         // warp n offset in tile

    if (tid == 0)
        for (int s = 0; s < 4; s++) mbar_init(smem_u32(&bar_full[s]), 1);
    __syncthreads();

    // global tile bases (bytes)
    const char* Ah = (const char*)Ahg + (size_t)mb * NC * 8192;
    const char* Al = (const char*)Alg + (size_t)mb * NC * 8192;
    const char* Bh = (const char*)Bhg + (size_t)nb * NC * 8192;
    const char* Bl = (const char*)Blg + (size_t)nb * NC * 8192;

    // prologue: stages 0..2
    if (tid == 0) {
        #pragma unroll
        for (int c = 0; c < 3; c++) {
            uint32_t fb = smem_u32(&bar_full[c]);
            mbar_expect(fb, STAGE);
            uint32_t d = sbase + c * STAGE;
            bulk_g2s(d,         Ah + (size_t)c * 8192, 8192, fb);
            bulk_g2s(d + 8192,  Al + (size_t)c * 8192, 8192, fb);
            bulk_g2s(d + 16384, Bh + (size_t)c * 8192, 8192, fb);
            bulk_g2s(d + 24576, Bl + (size_t)c * 8192, 8192, fb);
        }
    }

    // per-lane ldmatrix address pieces
    const int rowA = wm + (lane & 15);
    const uint32_t xa = (rowA >> 1) & 3;
    const uint32_t offA = (uint32_t)rowA * 64;
    const uint32_t cA[2] = { (((uint32_t)(lane >> 4) + 0) ^ xa) * 16,
                             (((uint32_t)(lane >> 4) + 2) ^ xa) * 16 };
    const int rowB = wn + (lane & 7);
    const uint32_t xb = (rowB >> 1) & 3;
    const uint32_t offB = (uint32_t)rowB * 64;
    const uint32_t cB[2] = { ((((uint32_t)(lane >> 3) & 1) + 0) ^ xb) * 16,
                             ((((uint32_t)(lane >> 3) & 1) + 2) ^ xb) * 16 };

    float acc[4][4][4];
    #pragma unroll
    for (int i = 0; i < 4; i++)
        #pragma unroll
        for (int j = 0; j < 4; j++)
            #pragma unroll
            for (int r = 0; r < 4; r++) acc[i][j][r] = 0.0f;

    #pragma unroll 1
    for (int c = 0; c < NC; c++) {
        // issue chunk c+3 (stage last consumed at c-1; safe after its sync)
        if (tid == 0 && c + 3 < NC) {
            int s = (c + 3) & 3;
            uint32_t fb = smem_u32(&bar_full[s]);
            mbar_expect(fb, STAGE);
            uint32_t d = sbase + s * STAGE;
            bulk_g2s(d,         Ah + (size_t)(c + 3) * 8192, 8192, fb);
            bulk_g2s(d + 8192,  Al + (size_t)(c + 3) * 8192, 8192, fb);
            bulk_g2s(d + 16384, Bh + (size_t)(c + 3) * 8192, 8192, fb);
            bulk_g2s(d + 24576, Bl + (size_t)(c + 3) * 8192, 8192, fb);
        }
        mbar_wait(smem_u32(&bar_full[c & 3]), (c >> 2) & 1);

        const uint32_t sb = sbase + (c & 3) * STAGE;
        #pragma unroll
        for (int kk = 0; kk < 2; kk++) {
            uint32_t ah[4][4], al[4][4];
            #pragma unroll
            for (int mi = 0; mi < 4; mi++) {
                LDSM4(ah[mi], sb + offA + mi * 1024 + cA[kk]);
                LDSM4(al[mi], sb + 8192 + offA + mi * 1024 + cA[kk]);
            }
            #pragma unroll
            for (int ni = 0; ni < 4; ni++) {
                uint32_t bh[2], bl[2];
                LDSM2(bh, sb + 16384 + offB + ni * 512 + cB[kk]);
                LDSM2(bl, sb + 24576 + offB + ni * 512 + cB[kk]);
                #pragma unroll
                for (int mi = 0; mi < 4; mi++) MMA16816(acc[mi][ni], ah[mi], bh);
                #pragma unroll
                for (int mi = 0; mi < 4; mi++) MMA16816(acc[mi][ni], al[mi], bh);
                #pragma unroll
                for (int mi = 0; mi < 4; mi++) MMA16816(acc[mi][ni], ah[mi], bl);
            }
        }
        __syncthreads();
    }

    // ---------------- epilogue ----------------
    #pragma unroll
    for (int mi = 0; mi < 4; mi++) {
        #pragma unroll
        for (int ni = 0; ni < 4; ni++) {
            const int n0 = nb * 128 + wn + ni * 8 + 2 * (lane & 3);
            const int m0 = mb * 128 + wm + mi * 16 + (lane >> 2);
            float2 bv = *(const float2*)(bias + n0);
            float v0 = acc[mi][ni][0] + bv.x;
            float v1 = acc[mi][ni][1] + bv.y;
            float v2 = acc[mi][ni][2] + bv.x;   // row m0+8, same cols
            float v3 = acc[mi][ni][3] + bv.y;
            if (MODE == 0) {
                v0 = (v0 >= 0.0f) ? v0 : NEG_SLOPE * v0;
                v1 = (v1 >= 0.0f) ? v1 : NEG_SLOPE * v1;
                v2 = (v2 >= 0.0f) ? v2 : NEG_SLOPE * v2;
                v3 = (v3 >= 0.0f) ? v3 : NEG_SLOPE * v3;
                __half h0, l0, h1, l1, h2, l2, h3, l3;
                split_h(v0, h0, l0); split_h(v1, h1, l1);
                split_h(v2, h2, l2); split_h(v3, h3, l3);
                size_t tile = (size_t)(m0 >> 7) * 32 + (n0 >> 5);
                uint32_t off = swz((uint32_t)(m0 & 127) * 64 + (uint32_t)(n0 & 31) * 2);
                char* ph = (char*)Ohi + tile * 8192;
                char* pl = (char*)Olo + tile * 8192;
                *(uint32_t*)(ph + off)       = pack_h2(h0, h1);
                *(uint32_t*)(pl + off)       = pack_h2(l0, l1);
                *(uint32_t*)(ph + off + 512) = pack_h2(h2, h3);   // m0+8: same xor
                *(uint32_t*)(pl + off + 512) = pack_h2(l2, l3);
            } else {
                float* p0 = Of + (size_t)m0 * Ntot + n0;
                *(float2*)p0                      = make_float2(tanhf(v0), tanhf(v1));
                *(float2*)(p0 + (size_t)8 * Ntot) = make_float2(tanhf(v2), tanhf(v3));
            }
        }
    }
}

// ---------------------------------------------------------------------------
// FK chain (validated in round 0, rel_err 8e-6)
// ---------------------------------------------------------------------------
__global__ __launch_bounds__(256) void fk_kernel(
    const float* __restrict__ joints, float* __restrict__ out)
{
    int row = blockIdx.x * blockDim.x + threadIdx.x;
    if (row >= BATCH) return;
    const float4* jq = (const float4*)(joints + (size_t)row * 256);
    float* o = out + (size_t)row * 192;

    float r00 = 1, r01 = 0, r02 = 0;
    float r10 = 0, r11 = 1, r12 = 0;
    float r20 = 0, r21 = 0, r22 = 1;
    float t0 = 0, t1 = 0, t2 = 0;

    #pragma unroll 4
    for (int j = 0; j < 64; j++) {
        float4 q = jq[j];
        float w = q.x, x = q.y, y = q.z, z = q.w;
        float s = 2.0f / (w * w + x * x + y * y + z * z);

        float R00 = 1.0f - s * (y * y + z * z);
        float R01 = s * (x * y - z * w);
        float R02 = s * (x * z + y * w);
        float R10 = s * (x * y + z * w);
        float R11 = 1.0f - s * (x * x + z * z);
        float R12 = s * (y * z - x * w);
        float R20 = s * (x * z - y * w);
        float R21 = s * (y * z + x * w);
        float R22 = 1.0f - s * (x * x + y * y);

        float n00 = r00 * R00 + r01 * R10 + r02 * R20;
        float n01 = r00 * R01 + r01 * R11 + r02 * R21;
        float n02 = r00 * R02 + r01 * R12 + r02 * R22;
        float n10 = r10 * R00 + r11 * R10 + r12 * R20;
        float n11 = r10 * R01 + r11 * R11 + r12 * R21;
        float n12 = r10 * R02 + r11 * R12 + r12 * R22;
        float n20 = r20 * R00 + r21 * R10 + r22 * R20;
        float n21 = r20 * R01 + r21 * R11 + r22 * R21;
        float n22 = r20 * R02 + r21 * R12 + r22 * R22;

        float nt0 = r00 * R01 + r01 * R11 + r02 * R21 + t0;
        float nt1 = r10 * R01 + r11 * R11 + r12 * R21 + t1;
        float nt2 = r20 * R01 + r21 * R11 + r22 * R21 + t2;

        r00 = n00; r01 = n01; r02 = n02;
        r10 = n10; r11 = n11; r12 = n12;
        r20 = n20; r21 = n21; r22 = n22;
        t0 = nt0; t1 = nt1; t2 = nt2;

        o[j * 3 + 0] = t0;
        o[j * 3 + 1] = t1;
        o[j * 3 + 2] = t2;
    }
}

// ---------------------------------------------------------------------------
// Launch
// ---------------------------------------------------------------------------
extern "C" void kernel_launch(void* const* d_in, const int* in_sizes, int n_in,
                              void* d_out, int out_size)
{
    const float* x  = (const float*)d_in[0];
    const float* W1 = (const float*)d_in[1];
    const float* b1 = (const float*)d_in[2];
    const float* W2 = (const float*)d_in[3];
    const float* b2 = (const float*)d_in[4];
    const float* W3 = (const float*)d_in[5];
    const float* b3 = (const float*)d_in[6];
    const float* W4 = (const float*)d_in[7];
    const float* b4 = (const float*)d_in[8];
    float* out = (float*)d_out;

    __half *a0h, *a0l, *a1h, *a1l, *w2h, *w2l, *w3h, *w3l, *w4h, *w4l;
    float* jnt;
    cudaGetSymbolAddress((void**)&a0h, g_a0h);
    cudaGetSymbolAddress((void**)&a0l, g_a0l);
    cudaGetSymbolAddress((void**)&a1h, g_a1h);
    cudaGetSymbolAddress((void**)&a1l, g_a1l);
    cudaGetSymbolAddress((void**)&w2h, g_w2h);
    cudaGetSymbolAddress((void**)&w2l, g_w2l);
    cudaGetSymbolAddress((void**)&w3h, g_w3h);
    cudaGetSymbolAddress((void**)&w3l, g_w3l);
    cudaGetSymbolAddress((void**)&w4h, g_w4h);
    cudaGetSymbolAddress((void**)&w4l, g_w4l);
    cudaGetSymbolAddress((void**)&jnt, g_joints);

    const int SMEM = 4 * 32768 + 1024;
    static int configured = -1;
    cudaFuncSetAttribute(gemm_kernel<0>, cudaFuncAttributeMaxDynamicSharedMemorySize, SMEM);
    cudaFuncSetAttribute(gemm_kernel<1>, cudaFuncAttributeMaxDynamicSharedMemorySize, SMEM);
    (void)configured;

    // producers (independent of each other)
    layer1_kernel<<<(BATCH * 128) / 256, 256>>>(x, W1, b1, a0h, a0l);
    wconv_kernel<<<(1024 * 128) / 256, 256>>>(W2, w2h, w2l, 1024);
    wconv_kernel<<<(1024 * 128) / 256, 256>>>(W3, w3h, w3l, 1024);
    wconv_kernel<<<(256 * 128) / 256, 256>>>(W4, w4h, w4l, 256);

    // L2: a0 @ W2 -> a1 (leaky)
    gemm_kernel<0><<<dim3(8, 128), 256, SMEM>>>(a0h, a0l, w2h, w2l, b2,
                                                a1h, a1l, nullptr, 1024);
    // L3: a1 @ W3 -> a0 (leaky)
    gemm_kernel<0><<<dim3(8, 128), 256, SMEM>>>(a1h, a1l, w3h, w3l, b3,
                                                a0h, a0l, nullptr, 1024);
    // L4: a0 @ W4 -> joints (tanh, fp32)
    gemm_kernel<1><<<dim3(2, 128), 256, SMEM>>>(a0h, a0l, w4h, w4l, b4,
                                                nullptr, nullptr, jnt, 256);
    // FK
    fk_kernel<<<BATCH / 256, 256>>>(jnt, out);
}

// round 4
// speedup vs baseline: 2.8987x; 1.0306x over previous
#include <cuda_runtime.h>
#include <cuda_fp16.h>
#include <math.h>
#include <stdint.h>

// ---------------------------------------------------------------------------
// fkopt_net round 4: mma.sync fp16x3-split GEMM, BK=64, 3-stage bulk pipeline,
// smem-staged epilogue with cp.async.bulk S2G stores.
// ---------------------------------------------------------------------------

#define BATCH 16384
#define KDIM  1024
#define NEG_SLOPE 0.01f

__device__ __align__(1024) __half g_a0h[BATCH * KDIM];
__device__ __align__(1024) __half g_a0l[BATCH * KDIM];
__device__ __align__(1024) __half g_a1h[BATCH * KDIM];
__device__ __align__(1024) __half g_a1l[BATCH * KDIM];
__device__ __align__(1024) __half g_w2h[KDIM * KDIM];
__device__ __align__(1024) __half g_w2l[KDIM * KDIM];
__device__ __align__(1024) __half g_w3h[KDIM * KDIM];
__device__ __align__(1024) __half g_w3l[KDIM * KDIM];
__device__ __align__(1024) __half g_w4h[256 * KDIM];
__device__ __align__(1024) __half g_w4l[256 * KDIM];
__device__ __align__(1024) float g_joints[BATCH * 256];

// ---------------- PTX helpers ----------------------------------------------
__device__ __forceinline__ uint32_t smem_u32(const void* p) {
    uint32_t a;
    asm("{ .reg .u64 t; cvta.to.shared.u64 t, %1; cvt.u32.u64 %0, t; }"
        : "=r"(a) : "l"(p));
    return a;
}
__device__ __forceinline__ void mbar_init(uint32_t a, uint32_t c) {
    asm volatile("mbarrier.init.shared.b64 [%0], %1;" :: "r"(a), "r"(c) : "memory");
}
__device__ __forceinline__ void mbar_expect(uint32_t a, uint32_t tx) {
    asm volatile("mbarrier.arrive.expect_tx.shared.b64 _, [%0], %1;"
                 :: "r"(a), "r"(tx) : "memory");
}
__device__ __forceinline__ void mbar_wait(uint32_t a, uint32_t ph) {
    asm volatile(
        "{\n\t.reg .pred P;\n\t"
        "WL_%=:\n\t"
        "mbarrier.try_wait.parity.acquire.cta.shared::cta.b64 P, [%0], %1, 0x989680;\n\t"
        "@P bra.uni WD_%=;\n\t"
        "bra.uni WL_%=;\n\t"
        "WD_%=:\n\t}"
        :: "r"(a), "r"(ph) : "memory");
}
__device__ __forceinline__ void bulk_g2s(uint32_t dst, const void* src,
                                         uint32_t bytes, uint32_t mbar) {
    asm volatile(
        "cp.async.bulk.shared::cluster.global.mbarrier::complete_tx::bytes "
        "[%0], [%1], %2, [%3];"
        :: "r"(dst), "l"(src), "r"(bytes), "r"(mbar) : "memory");
}
__device__ __forceinline__ void bulk_s2g(void* dst, uint32_t src, uint32_t bytes) {
    asm volatile(
        "cp.async.bulk.global.shared::cta.bulk_group [%0], [%1], %2;"
        :: "l"(dst), "r"(src), "r"(bytes) : "memory");
}

#define LDSM4(r, a)                                                              \
    asm volatile("ldmatrix.sync.aligned.m8n8.x4.shared.b16 {%0,%1,%2,%3}, [%4];" \
                 : "=r"((r)[0]), "=r"((r)[1]), "=r"((r)[2]), "=r"((r)[3])        \
                 : "r"(a))
#define LDSM2(r, a)                                                              \
    asm volatile("ldmatrix.sync.aligned.m8n8.x2.shared.b16 {%0,%1}, [%2];"       \
                 : "=r"((r)[0]), "=r"((r)[1]) : "r"(a))
#define MMA16816(d, a, b)                                                        \
    asm volatile("mma.sync.aligned.m16n8k16.row.col.f32.f16.f16.f32 "            \
                 "{%0,%1,%2,%3}, {%4,%5,%6,%7}, {%8,%9}, {%0,%1,%2,%3};"         \
                 : "+f"((d)[0]), "+f"((d)[1]), "+f"((d)[2]), "+f"((d)[3])        \
                 : "r"((a)[0]), "r"((a)[1]), "r"((a)[2]), "r"((a)[3]),           \
                   "r"((b)[0]), "r"((b)[1]))

// tile byte-offset swizzle: off = row*64 + col*2 (32 fp16 cols per row)
__device__ __forceinline__ uint32_t swz(uint32_t off) {
    return off ^ (((off >> 7) & 3u) << 4);
}
__device__ __forceinline__ void split_h(float v, __half& h, __half& l) {
    h = __float2half_rn(v);
    l = __float2half_rn(v - __half2float(h));
}
__device__ __forceinline__ uint32_t pack_h2(__half a, __half b) {
    return ((uint32_t)__half_as_ushort(b) << 16) | (uint32_t)__half_as_ushort(a);
}

// ---------------------------------------------------------------------------
// Layer 1 producer (unchanged, validated)
// ---------------------------------------------------------------------------
__global__ __launch_bounds__(256) void layer1_kernel(
    const float* __restrict__ x, const float* __restrict__ W1,
    const float* __restrict__ b1,
    __half* __restrict__ Ohi, __half* __restrict__ Olo)
{
    int idx = blockIdx.x * 256 + threadIdx.x;
    int n0 = (idx & 127) * 8;
    int m  = idx >> 7;
    float x0 = __ldg(x + m * 3 + 0);
    float x1 = __ldg(x + m * 3 + 1);
    float x2 = __ldg(x + m * 3 + 2);

    uint32_t hw[4], lw[4];
    #pragma unroll
    for (int p = 0; p < 4; p++) {
        int n = n0 + 2 * p;
        float v0 = __ldg(b1 + n) + x0 * __ldg(W1 + n) +
                   x1 * __ldg(W1 + 1024 + n) + x2 * __ldg(W1 + 2048 + n);
        float v1 = __ldg(b1 + n + 1) + x0 * __ldg(W1 + n + 1) +
                   x1 * __ldg(W1 + 1024 + n + 1) + x2 * __ldg(W1 + 2048 + n + 1);
        v0 = (v0 >= 0.0f) ? v0 : NEG_SLOPE * v0;
        v1 = (v1 >= 0.0f) ? v1 : NEG_SLOPE * v1;
        __half h0, l0, h1, l1;
        split_h(v0, h0, l0); split_h(v1, h1, l1);
        hw[p] = pack_h2(h0, h1);
        lw[p] = pack_h2(l0, l1);
    }
    size_t tile = (size_t)(m >> 7) * 32 + (n0 >> 5);
    uint32_t off = swz((uint32_t)(m & 127) * 64 + (uint32_t)(n0 & 31) * 2);
    *(uint4*)((char*)Ohi + tile * 8192 + off) = make_uint4(hw[0], hw[1], hw[2], hw[3]);
    *(uint4*)((char*)Olo + tile * 8192 + off) = make_uint4(lw[0], lw[1], lw[2], lw[3]);
}

// ---------------------------------------------------------------------------
// Weight convert+transpose producer (unchanged, validated)
// ---------------------------------------------------------------------------
__global__ __launch_bounds__(256) void wconv_kernel(
    const float* __restrict__ W,
    __half* __restrict__ Ohi, __half* __restrict__ Olo, int N)
{
    int idx = blockIdx.x * 256 + threadIdx.x;
    int n  = idx % N;
    int k0 = (idx / N) * 8;
    uint32_t hw[4], lw[4];
    #pragma unroll
    for (int p = 0; p < 4; p++) {
        float v0 = __ldg(W + (size_t)(k0 + 2 * p) * N + n);
        float v1 = __ldg(W + (size_t)(k0 + 2 * p + 1) * N + n);
        __half h0, l0, h1, l1;
        split_h(v0, h0, l0); split_h(v1, h1, l1);
        hw[p] = pack_h2(h0, h1);
        lw[p] = pack_h2(l0, l1);
    }
    size_t tile = (size_t)(n >> 7) * 32 + (k0 >> 5);
    uint32_t off = swz((uint32_t)(n & 127) * 64 + (uint32_t)(k0 & 31) * 2);
    *(uint4*)((char*)Ohi + tile * 8192 + off) = make_uint4(hw[0], hw[1], hw[2], hw[3]);
    *(uint4*)((char*)Olo + tile * 8192 + off) = make_uint4(lw[0], lw[1], lw[2], lw[3]);
}

// ---------------------------------------------------------------------------
// GEMM: C[16384, Ntot] = act(A @ W + bias), fp16x3 mma.sync.
// CTA tile 128x128, BK=64 (16 chunks), 3-stage bulk pipeline (64KB/stage).
// Stage layout: Ah(16K) Al(16K) Bh(16K) Bl(16K); each 16K = 2 adjacent 8K tiles.
// Epilogue: smem-staged, cp.async.bulk S2G.
// ---------------------------------------------------------------------------
template <int MODE>
__global__ __launch_bounds__(256, 1) void gemm_kernel(
    const __half* __restrict__ Ahg, const __half* __restrict__ Alg,
    const __half* __restrict__ Bhg, const __half* __restrict__ Blg,
    const float* __restrict__ bias,
    __half* __restrict__ Ohi, __half* __restrict__ Olo,
    float* __restrict__ Of, int Ntot)
{
    constexpr int NC = 16;                  // K=1024 / BK=64
    constexpr uint32_t STAGE = 65536;
    __shared__ __align__(8) uint64_t bar_full[3];
    extern __shared__ char dsm[];
    const uint32_t sbase = (smem_u32(dsm) + 1023) & ~1023u;

    const int tid = threadIdx.x, lane = tid & 31, wid = tid >> 5;
    const int mb = blockIdx.y, nb = blockIdx.x;
    const int wm = (wid & 1) * 64;
    const int wn = (wid >> 1) * 32;

    if (tid == 0)
        for (int s = 0; s < 3; s++) mbar_init(smem_u32(&bar_full[s]), 1);
    __syncthreads();

    const char* Ah = (const char*)Ahg + (size_t)mb * 32 * 8192;
    const char* Al = (const char*)Alg + (size_t)mb * 32 * 8192;
    const char* Bh = (const char*)Bhg + (size_t)nb * 32 * 8192;
    const char* Bl = (const char*)Blg + (size_t)nb * 32 * 8192;

    // prologue: stages 0,1
    if (tid == 0) {
        #pragma unroll
        for (int c = 0; c < 2; c++) {
            uint32_t fb = smem_u32(&bar_full[c]);
            mbar_expect(fb, STAGE);
            uint32_t d = sbase + c * STAGE;
            bulk_g2s(d,         Ah + (size_t)c * 16384, 16384, fb);
            bulk_g2s(d + 16384, Al + (size_t)c * 16384, 16384, fb);
            bulk_g2s(d + 32768, Bh + (size_t)c * 16384, 16384, fb);
            bulk_g2s(d + 49152, Bl + (size_t)c * 16384, 16384, fb);
        }
    }

    // per-lane ldmatrix addressing (within an 8KB tile)
    const int rowA = wm + (lane & 15);
    const uint32_t xa = (rowA >> 1) & 3;
    const uint32_t offA = (uint32_t)rowA * 64;
    const uint32_t cA[2] = { (((uint32_t)(lane >> 4) + 0) ^ xa) * 16,
                             (((uint32_t)(lane >> 4) + 2) ^ xa) * 16 };
    const int rowB = wn + (lane & 7);
    const uint32_t xb = (rowB >> 1) & 3;
    const uint32_t offB = (uint32_t)rowB * 64;
    const uint32_t cB[2] = { ((((uint32_t)(lane >> 3) & 1) + 0) ^ xb) * 16,
                             ((((uint32_t)(lane >> 3) & 1) + 2) ^ xb) * 16 };

    float acc[4][4][4];
    #pragma unroll
    for (int i = 0; i < 4; i++)
        #pragma unroll
        for (int j = 0; j < 4; j++)
            #pragma unroll
            for (int r = 0; r < 4; r++) acc[i][j][r] = 0.0f;

    #pragma unroll 1
    for (int c = 0; c < NC; c++) {
        if (tid == 0 && c + 2 < NC) {
            int s = (c + 2) % 3;
            uint32_t fb = smem_u32(&bar_full[s]);
            mbar_expect(fb, STAGE);
            uint32_t d = sbase + s * STAGE;
            bulk_g2s(d,         Ah + (size_t)(c + 2) * 16384, 16384, fb);
            bulk_g2s(d + 16384, Al + (size_t)(c + 2) * 16384, 16384, fb);
            bulk_g2s(d + 32768, Bh + (size_t)(c + 2) * 16384, 16384, fb);
            bulk_g2s(d + 49152, Bl + (size_t)(c + 2) * 16384, 16384, fb);
        }
        mbar_wait(smem_u32(&bar_full[c % 3]), (c / 3) & 1);

        const uint32_t sb = sbase + (c % 3) * STAGE;
        #pragma unroll
        for (int kk = 0; kk < 4; kk++) {
            const uint32_t toff = (uint32_t)(kk >> 1) * 8192;
            const uint32_t ca = cA[kk & 1], cb = cB[kk & 1];
            uint32_t ah[4][4], al[4][4];
            #pragma unroll
            for (int mi = 0; mi < 4; mi++) {
                LDSM4(ah[mi], sb + toff + offA + mi * 1024 + ca);
                LDSM4(al[mi], sb + 16384 + toff + offA + mi * 1024 + ca);
            }
            #pragma unroll
            for (int ni = 0; ni < 4; ni++) {
                uint32_t bh[2], bl[2];
                LDSM2(bh, sb + 32768 + toff + offB + ni * 512 + cb);
                LDSM2(bl, sb + 49152 + toff + offB + ni * 512 + cb);
                #pragma unroll
                for (int mi = 0; mi < 4; mi++) MMA16816(acc[mi][ni], ah[mi], bh);
                #pragma unroll
                for (int mi = 0; mi < 4; mi++) MMA16816(acc[mi][ni], al[mi], bh);
                #pragma unroll
                for (int mi = 0; mi < 4; mi++) MMA16816(acc[mi][ni], ah[mi], bl);
            }
        }
        __syncthreads();
    }

    // ---------------- epilogue: stage C in smem, bulk-copy out --------------
    if (MODE == 0) {
        // smem image: 4 hi tiles (32KB) then 4 lo tiles (32KB)
        const uint32_t chi = sbase, clo = sbase + 32768;
        #pragma unroll
        for (int mi = 0; mi < 4; mi++) {
            #pragma unroll
            for (int ni = 0; ni < 4; ni++) {
                const int nl = wn + ni * 8 + 2 * (lane & 3);   // CTA-local col
                const int rl = wm + mi * 16 + (lane >> 2);      // CTA-local row
                float2 bv = *(const float2*)(bias + nb * 128 + nl);
                float v0 = acc[mi][ni][0] + bv.x;
                float v1 = acc[mi][ni][1] + bv.y;
                float v2 = acc[mi][ni][2] + bv.x;
                float v3 = acc[mi][ni][3] + bv.y;
                v0 = (v0 >= 0.0f) ? v0 : NEG_SLOPE * v0;
                v1 = (v1 >= 0.0f) ? v1 : NEG_SLOPE * v1;
                v2 = (v2 >= 0.0f) ? v2 : NEG_SLOPE * v2;
                v3 = (v3 >= 0.0f) ? v3 : NEG_SLOPE * v3;
                __half h0, l0, h1, l1, h2, l2, h3, l3;
                split_h(v0, h0, l0); split_h(v1, h1, l1);
                split_h(v2, h2, l2); split_h(v3, h3, l3);
                const uint32_t tb = (uint32_t)(nl >> 5) * 8192;
                const uint32_t off = swz((uint32_t)rl * 64 + (uint32_t)(nl & 31) * 2);
                *(uint32_t*)(dsm + (chi - smem_u32(dsm)) + tb + off) = 0; // placeholder avoided
                // direct smem stores via address arithmetic:
                asm volatile("st.shared.b32 [%0], %1;" :: "r"(chi + tb + off),       "r"(pack_h2(h0, h1)) : "memory");
                asm volatile("st.shared.b32 [%0], %1;" :: "r"(chi + tb + off + 512), "r"(pack_h2(h2, h3)) : "memory");
                asm volatile("st.shared.b32 [%0], %1;" :: "r"(clo + tb + off),       "r"(pack_h2(l0, l1)) : "memory");
                asm volatile("st.shared.b32 [%0], %1;" :: "r"(clo + tb + off + 512), "r"(pack_h2(l2, l3)) : "memory");
            }
        }
        __syncthreads();
        if (tid == 0) {
            asm volatile("fence.proxy.async;" ::: "memory");
            const size_t tbase = (size_t)mb * 32 + (size_t)nb * 4;
            #pragma unroll
            for (int t = 0; t < 4; t++) {
                bulk_s2g((char*)Ohi + (tbase + t) * 8192, chi + t * 8192, 8192);
                bulk_s2g((char*)Olo + (tbase + t) * 8192, clo + t * 8192, 8192);
            }
            asm volatile("cp.async.bulk.commit_group;" ::: "memory");
            asm volatile("cp.async.bulk.wait_group 0;" ::: "memory");
        }
    } else {
        // fp32 128x128 tile, row-major rows of 512B
        const uint32_t cf = sbase;
        #pragma unroll
        for (int mi = 0; mi < 4; mi++) {
            #pragma unroll
            for (int ni = 0; ni < 4; ni++) {
                const int nl = wn + ni * 8 + 2 * (lane & 3);
                const int rl = wm + mi * 16 + (lane >> 2);
                float2 bv = *(const float2*)(bias + nb * 128 + nl);
                float2 p0 = make_float2(tanhf(acc[mi][ni][0] + bv.x),
                                        tanhf(acc[mi][ni][1] + bv.y));
                float2 p1 = make_float2(tanhf(acc[mi][ni][2] + bv.x),
                                        tanhf(acc[mi][ni][3] + bv.y));
                uint32_t a0 = cf + (uint32_t)rl * 512 + (uint32_t)nl * 4;
                asm volatile("st.shared.v2.f32 [%0], {%1, %2};"
                             :: "r"(a0), "f"(p0.x), "f"(p0.y) : "memory");
                asm volatile("st.shared.v2.f32 [%0], {%1, %2};"
                             :: "r"(a0 + 8 * 512), "f"(p1.x), "f"(p1.y) : "memory");
            }
        }
        __syncthreads();
        // coalesced copy-out: 4096 uint4 (64KB)
        const float* sf = (const float*)dsm;     // == cf region (dsm aligned)
        const uint32_t cf_off = cf - smem_u32(dsm);
        #pragma unroll
        for (int p = 0; p < 16; p++) {
            int idx = p * 256 + tid;             // 0..4095
            int r = idx >> 5;                    // row 0..127
            int c4 = idx & 31;                   // 16B unit in row
            uint4 v = *(const uint4*)((const char*)sf + cf_off + r * 512 + c4 * 16);
            *(uint4*)(Of + (size_t)(mb * 128 + r) * Ntot + nb * 128 + c4 * 4) = v;
        }
    }
}

// ---------------------------------------------------------------------------
// FK chain (validated)
// ---------------------------------------------------------------------------
__global__ __launch_bounds__(256) void fk_kernel(
    const float* __restrict__ joints, float* __restrict__ out)
{
    int row = blockIdx.x * blockDim.x + threadIdx.x;
    if (row >= BATCH) return;
    const float4* jq = (const float4*)(joints + (size_t)row * 256);
    float* o = out + (size_t)row * 192;

    float r00 = 1, r01 = 0, r02 = 0;
    float r10 = 0, r11 = 1, r12 = 0;
    float r20 = 0, r21 = 0, r22 = 1;
    float t0 = 0, t1 = 0, t2 = 0;

    #pragma unroll 4
    for (int j = 0; j < 64; j++) {
        float4 q = jq[j];
        float w = q.x, x = q.y, y = q.z, z = q.w;
        float s = 2.0f / (w * w + x * x + y * y + z * z);

        float R00 = 1.0f - s * (y * y + z * z);
        float R01 = s * (x * y - z * w);
        float R02 = s * (x * z + y * w);
        float R10 = s * (x * y + z * w);
        float R11 = 1.0f - s * (x * x + z * z);
        float R12 = s * (y * z - x * w);
        float R20 = s * (x * z - y * w);
        float R21 = s * (y * z + x * w);
        float R22 = 1.0f - s * (x * x + y * y);

        float n00 = r00 * R00 + r01 * R10 + r02 * R20;
        float n01 = r00 * R01 + r01 * R11 + r02 * R21;
        float n02 = r00 * R02 + r01 * R12 + r02 * R22;
        float n10 = r10 * R00 + r11 * R10 + r12 * R20;
        float n11 = r10 * R01 + r11 * R11 + r12 * R21;
        float n12 = r10 * R02 + r11 * R12 + r12 * R22;
        float n20 = r20 * R00 + r21 * R10 + r22 * R20;
        float n21 = r20 * R01 + r21 * R11 + r22 * R21;
        float n22 = r20 * R02 + r21 * R12 + r22 * R22;

        float nt0 = r00 * R01 + r01 * R11 + r02 * R21 + t0;
        float nt1 = r10 * R01 + r11 * R11 + r12 * R21 + t1;
        float nt2 = r20 * R01 + r21 * R11 + r22 * R21 + t2;

        r00 = n00; r01 = n01; r02 = n02;
        r10 = n10; r11 = n11; r12 = n12;
        r20 = n20; r21 = n21; r22 = n22;
        t0 = nt0; t1 = nt1; t2 = nt2;

        o[j * 3 + 0] = t0;
        o[j * 3 + 1] = t1;
        o[j * 3 + 2] = t2;
    }
}

// ---------------------------------------------------------------------------
// Launch
// ---------------------------------------------------------------------------
extern "C" void kernel_launch(void* const* d_in, const int* in_sizes, int n_in,
                              void* d_out, int out_size)
{
    const float* x  = (const float*)d_in[0];
    const float* W1 = (const float*)d_in[1];
    const float* b1 = (const float*)d_in[2];
    const float* W2 = (const float*)d_in[3];
    const float* b2 = (const float*)d_in[4];
    const float* W3 = (const float*)d_in[5];
    const float* b3 = (const float*)d_in[6];
    const float* W4 = (const float*)d_in[7];
    const float* b4 = (const float*)d_in[8];
    float* out = (float*)d_out;

    __half *a0h, *a0l, *a1h, *a1l, *w2h, *w2l, *w3h, *w3l, *w4h, *w4l;
    float* jnt;
    cudaGetSymbolAddress((void**)&a0h, g_a0h);
    cudaGetSymbolAddress((void**)&a0l, g_a0l);
    cudaGetSymbolAddress((void**)&a1h, g_a1h);
    cudaGetSymbolAddress((void**)&a1l, g_a1l);
    cudaGetSymbolAddress((void**)&w2h, g_w2h);
    cudaGetSymbolAddress((void**)&w2l, g_w2l);
    cudaGetSymbolAddress((void**)&w3h, g_w3h);
    cudaGetSymbolAddress((void**)&w3l, g_w3l);
    cudaGetSymbolAddress((void**)&w4h, g_w4h);
    cudaGetSymbolAddress((void**)&w4l, g_w4l);
    cudaGetSymbolAddress((void**)&jnt, g_joints);

    const int SMEM = 3 * 65536 + 1024;   // 197632
    cudaFuncSetAttribute(gemm_kernel<0>, cudaFuncAttributeMaxDynamicSharedMemorySize, SMEM);
    cudaFuncSetAttribute(gemm_kernel<1>, cudaFuncAttributeMaxDynamicSharedMemorySize, SMEM);

    layer1_kernel<<<(BATCH * 128) / 256, 256>>>(x, W1, b1, a0h, a0l);
    wconv_kernel<<<(1024 * 128) / 256, 256>>>(W2, w2h, w2l, 1024);
    wconv_kernel<<<(1024 * 128) / 256, 256>>>(W3, w3h, w3l, 1024);
    wconv_kernel<<<(256 * 128) / 256, 256>>>(W4, w4h, w4l, 256);

    gemm_kernel<0><<<dim3(8, 128), 256, SMEM>>>(a0h, a0l, w2h, w2l, b2,
                                                a1h, a1l, nullptr, 1024);
    gemm_kernel<0><<<dim3(8, 128), 256, SMEM>>>(a1h, a1l, w3h, w3l, b3,
                                                a0h, a0l, nullptr, 1024);
    gemm_kernel<1><<<dim3(2, 128), 256, SMEM>>>(a0h, a0l, w4h, w4l, b4,
                                                nullptr, nullptr, jnt, 256);
    fk_kernel<<<BATCH / 256, 256>>>(jnt, out);
}

// round 5
// speedup vs baseline: 3.0929x; 1.0670x over previous
#include <cuda_runtime.h>
#include <cuda_fp16.h>
#include <math.h>
#include <stdint.h>

// ---------------------------------------------------------------------------
// fkopt_net round 5: mma.sync fp16x3 GEMM, BK=32, 3-stage x 32KB pipeline,
// 2 CTAs/SM (__launch_bounds__(256,2)) to overlap per-chunk sync bubbles.
// ---------------------------------------------------------------------------

#define BATCH 16384
#define KDIM  1024
#define NEG_SLOPE 0.01f

__device__ __align__(1024) __half g_a0h[BATCH * KDIM];
__device__ __align__(1024) __half g_a0l[BATCH * KDIM];
__device__ __align__(1024) __half g_a1h[BATCH * KDIM];
__device__ __align__(1024) __half g_a1l[BATCH * KDIM];
__device__ __align__(1024) __half g_w2h[KDIM * KDIM];
__device__ __align__(1024) __half g_w2l[KDIM * KDIM];
__device__ __align__(1024) __half g_w3h[KDIM * KDIM];
__device__ __align__(1024) __half g_w3l[KDIM * KDIM];
__device__ __align__(1024) __half g_w4h[256 * KDIM];
__device__ __align__(1024) __half g_w4l[256 * KDIM];
__device__ __align__(1024) float g_joints[BATCH * 256];

// ---------------- PTX helpers ----------------------------------------------
__device__ __forceinline__ uint32_t smem_u32(const void* p) {
    uint32_t a;
    asm("{ .reg .u64 t; cvta.to.shared.u64 t, %1; cvt.u32.u64 %0, t; }"
        : "=r"(a) : "l"(p));
    return a;
}
__device__ __forceinline__ void mbar_init(uint32_t a, uint32_t c) {
    asm volatile("mbarrier.init.shared.b64 [%0], %1;" :: "r"(a), "r"(c) : "memory");
}
__device__ __forceinline__ void mbar_expect(uint32_t a, uint32_t tx) {
    asm volatile("mbarrier.arrive.expect_tx.shared.b64 _, [%0], %1;"
                 :: "r"(a), "r"(tx) : "memory");
}
__device__ __forceinline__ void mbar_wait(uint32_t a, uint32_t ph) {
    asm volatile(
        "{\n\t.reg .pred P;\n\t"
        "WL_%=:\n\t"
        "mbarrier.try_wait.parity.acquire.cta.shared::cta.b64 P, [%0], %1, 0x989680;\n\t"
        "@P bra.uni WD_%=;\n\t"
        "bra.uni WL_%=;\n\t"
        "WD_%=:\n\t}"
        :: "r"(a), "r"(ph) : "memory");
}
__device__ __forceinline__ void bulk_g2s(uint32_t dst, const void* src,
                                         uint32_t bytes, uint32_t mbar) {
    asm volatile(
        "cp.async.bulk.shared::cluster.global.mbarrier::complete_tx::bytes "
        "[%0], [%1], %2, [%3];"
        :: "r"(dst), "l"(src), "r"(bytes), "r"(mbar) : "memory");
}
__device__ __forceinline__ void bulk_s2g(void* dst, uint32_t src, uint32_t bytes) {
    asm volatile(
        "cp.async.bulk.global.shared::cta.bulk_group [%0], [%1], %2;"
        :: "l"(dst), "r"(src), "r"(bytes) : "memory");
}

#define LDSM4(r, a)                                                              \
    asm volatile("ldmatrix.sync.aligned.m8n8.x4.shared.b16 {%0,%1,%2,%3}, [%4];" \
                 : "=r"((r)[0]), "=r"((r)[1]), "=r"((r)[2]), "=r"((r)[3])        \
                 : "r"(a))
#define LDSM2(r, a)                                                              \
    asm volatile("ldmatrix.sync.aligned.m8n8.x2.shared.b16 {%0,%1}, [%2];"       \
                 : "=r"((r)[0]), "=r"((r)[1]) : "r"(a))
#define MMA16816(d, a, b)                                                        \
    asm volatile("mma.sync.aligned.m16n8k16.row.col.f32.f16.f16.f32 "            \
                 "{%0,%1,%2,%3}, {%4,%5,%6,%7}, {%8,%9}, {%0,%1,%2,%3};"         \
                 : "+f"((d)[0]), "+f"((d)[1]), "+f"((d)[2]), "+f"((d)[3])        \
                 : "r"((a)[0]), "r"((a)[1]), "r"((a)[2]), "r"((a)[3]),           \
                   "r"((b)[0]), "r"((b)[1]))

// tile byte-offset swizzle: off = row*64 + col*2 (32 fp16 cols per row)
__device__ __forceinline__ uint32_t swz(uint32_t off) {
    return off ^ (((off >> 7) & 3u) << 4);
}
__device__ __forceinline__ void split_h(float v, __half& h, __half& l) {
    h = __float2half_rn(v);
    l = __float2half_rn(v - __half2float(h));
}
__device__ __forceinline__ uint32_t pack_h2(__half a, __half b) {
    return ((uint32_t)__half_as_ushort(b) << 16) | (uint32_t)__half_as_ushort(a);
}

// ---------------------------------------------------------------------------
// Layer 1 producer (validated)
// ---------------------------------------------------------------------------
__global__ __launch_bounds__(256) void layer1_kernel(
    const float* __restrict__ x, const float* __restrict__ W1,
    const float* __restrict__ b1,
    __half* __restrict__ Ohi, __half* __restrict__ Olo)
{
    int idx = blockIdx.x * 256 + threadIdx.x;
    int n0 = (idx & 127) * 8;
    int m  = idx >> 7;
    float x0 = __ldg(x + m * 3 + 0);
    float x1 = __ldg(x + m * 3 + 1);
    float x2 = __ldg(x + m * 3 + 2);

    uint32_t hw[4], lw[4];
    #pragma unroll
    for (int p = 0; p < 4; p++) {
        int n = n0 + 2 * p;
        float v0 = __ldg(b1 + n) + x0 * __ldg(W1 + n) +
                   x1 * __ldg(W1 + 1024 + n) + x2 * __ldg(W1 + 2048 + n);
        float v1 = __ldg(b1 + n + 1) + x0 * __ldg(W1 + n + 1) +
                   x1 * __ldg(W1 + 1024 + n + 1) + x2 * __ldg(W1 + 2048 + n + 1);
        v0 = (v0 >= 0.0f) ? v0 : NEG_SLOPE * v0;
        v1 = (v1 >= 0.0f) ? v1 : NEG_SLOPE * v1;
        __half h0, l0, h1, l1;
        split_h(v0, h0, l0); split_h(v1, h1, l1);
        hw[p] = pack_h2(h0, h1);
        lw[p] = pack_h2(l0, l1);
    }
    size_t tile = (size_t)(m >> 7) * 32 + (n0 >> 5);
    uint32_t off = swz((uint32_t)(m & 127) * 64 + (uint32_t)(n0 & 31) * 2);
    *(uint4*)((char*)Ohi + tile * 8192 + off) = make_uint4(hw[0], hw[1], hw[2], hw[3]);
    *(uint4*)((char*)Olo + tile * 8192 + off) = make_uint4(lw[0], lw[1], lw[2], lw[3]);
}

// ---------------------------------------------------------------------------
// Weight convert+transpose producer (validated)
// ---------------------------------------------------------------------------
__global__ __launch_bounds__(256) void wconv_kernel(
    const float* __restrict__ W,
    __half* __restrict__ Ohi, __half* __restrict__ Olo, int N)
{
    int idx = blockIdx.x * 256 + threadIdx.x;
    int n  = idx % N;
    int k0 = (idx / N) * 8;
    uint32_t hw[4], lw[4];
    #pragma unroll
    for (int p = 0; p < 4; p++) {
        float v0 = __ldg(W + (size_t)(k0 + 2 * p) * N + n);
        float v1 = __ldg(W + (size_t)(k0 + 2 * p + 1) * N + n);
        __half h0, l0, h1, l1;
        split_h(v0, h0, l0); split_h(v1, h1, l1);
        hw[p] = pack_h2(h0, h1);
        lw[p] = pack_h2(l0, l1);
    }
    size_t tile = (size_t)(n >> 7) * 32 + (k0 >> 5);
    uint32_t off = swz((uint32_t)(n & 127) * 64 + (uint32_t)(k0 & 31) * 2);
    *(uint4*)((char*)Ohi + tile * 8192 + off) = make_uint4(hw[0], hw[1], hw[2], hw[3]);
    *(uint4*)((char*)Olo + tile * 8192 + off) = make_uint4(lw[0], lw[1], lw[2], lw[3]);
}

// ---------------------------------------------------------------------------
// GEMM: C[16384, Ntot] = act(A @ W + bias), fp16x3 mma.sync.
// CTA tile 128x128, BK=32 (32 chunks), 3-stage x 32KB pipeline, 2 CTAs/SM.
// Stage layout: Ah(8K) Al(8K) Bh(8K) Bl(8K). Epilogue: smem-staged bulk S2G.
// ---------------------------------------------------------------------------
template <int MODE>
__global__ __launch_bounds__(256, 2) void gemm_kernel(
    const __half* __restrict__ Ahg, const __half* __restrict__ Alg,
    const __half* __restrict__ Bhg, const __half* __restrict__ Blg,
    const float* __restrict__ bias,
    __half* __restrict__ Ohi, __half* __restrict__ Olo,
    float* __restrict__ Of, int Ntot)
{
    constexpr int NC = 32;                  // K=1024 / BK=32
    constexpr uint32_t STAGE = 32768;
    __shared__ __align__(8) uint64_t bar_full[3];
    extern __shared__ char dsm[];
    const uint32_t sbase = (smem_u32(dsm) + 1023) & ~1023u;

    const int tid = threadIdx.x, lane = tid & 31, wid = tid >> 5;
    const int mb = blockIdx.y, nb = blockIdx.x;
    const int wm = (wid & 1) * 64;
    const int wn = (wid >> 1) * 32;

    if (tid == 0)
        for (int s = 0; s < 3; s++) mbar_init(smem_u32(&bar_full[s]), 1);
    __syncthreads();

    const char* Ah = (const char*)Ahg + (size_t)mb * 32 * 8192;
    const char* Al = (const char*)Alg + (size_t)mb * 32 * 8192;
    const char* Bh = (const char*)Bhg + (size_t)nb * 32 * 8192;
    const char* Bl = (const char*)Blg + (size_t)nb * 32 * 8192;

    // prologue: stages 0,1
    if (tid == 0) {
        #pragma unroll
        for (int c = 0; c < 2; c++) {
            uint32_t fb = smem_u32(&bar_full[c]);
            mbar_expect(fb, STAGE);
            uint32_t d = sbase + c * STAGE;
            bulk_g2s(d,         Ah + (size_t)c * 8192, 8192, fb);
            bulk_g2s(d + 8192,  Al + (size_t)c * 8192, 8192, fb);
            bulk_g2s(d + 16384, Bh + (size_t)c * 8192, 8192, fb);
            bulk_g2s(d + 24576, Bl + (size_t)c * 8192, 8192, fb);
        }
    }

    // per-lane ldmatrix addressing (within an 8KB tile)
    const int rowA = wm + (lane & 15);
    const uint32_t xa = (rowA >> 1) & 3;
    const uint32_t offA = (uint32_t)rowA * 64;
    const uint32_t cA[2] = { (((uint32_t)(lane >> 4) + 0) ^ xa) * 16,
                             (((uint32_t)(lane >> 4) + 2) ^ xa) * 16 };
    const int rowB = wn + (lane & 7);
    const uint32_t xb = (rowB >> 1) & 3;
    const uint32_t offB = (uint32_t)rowB * 64;
    const uint32_t cB[2] = { ((((uint32_t)(lane >> 3) & 1) + 0) ^ xb) * 16,
                             ((((uint32_t)(lane >> 3) & 1) + 2) ^ xb) * 16 };

    float acc[4][4][4];
    #pragma unroll
    for (int i = 0; i < 4; i++)
        #pragma unroll
        for (int j = 0; j < 4; j++)
            #pragma unroll
            for (int r = 0; r < 4; r++) acc[i][j][r] = 0.0f;

    #pragma unroll 1
    for (int c = 0; c < NC; c++) {
        if (tid == 0 && c + 2 < NC) {
            int s = (c + 2) % 3;
            uint32_t fb = smem_u32(&bar_full[s]);
            mbar_expect(fb, STAGE);
            uint32_t d = sbase + s * STAGE;
            bulk_g2s(d,         Ah + (size_t)(c + 2) * 8192, 8192, fb);
            bulk_g2s(d + 8192,  Al + (size_t)(c + 2) * 8192, 8192, fb);
            bulk_g2s(d + 16384, Bh + (size_t)(c + 2) * 8192, 8192, fb);
            bulk_g2s(d + 24576, Bl + (size_t)(c + 2) * 8192, 8192, fb);
        }
        mbar_wait(smem_u32(&bar_full[c % 3]), (c / 3) & 1);

        const uint32_t sb = sbase + (c % 3) * STAGE;
        #pragma unroll
        for (int kk = 0; kk < 2; kk++) {
            const uint32_t ca = cA[kk], cb = cB[kk];
            uint32_t ah[4][4], al[4][4];
            #pragma unroll
            for (int mi = 0; mi < 4; mi++) {
                LDSM4(ah[mi], sb + offA + mi * 1024 + ca);
                LDSM4(al[mi], sb + 8192 + offA + mi * 1024 + ca);
            }
            #pragma unroll
            for (int ni = 0; ni < 4; ni++) {
                uint32_t bh[2], bl[2];
                LDSM2(bh, sb + 16384 + offB + ni * 512 + cb);
                LDSM2(bl, sb + 24576 + offB + ni * 512 + cb);
                #pragma unroll
                for (int mi = 0; mi < 4; mi++) MMA16816(acc[mi][ni], ah[mi], bh);
                #pragma unroll
                for (int mi = 0; mi < 4; mi++) MMA16816(acc[mi][ni], al[mi], bh);
                #pragma unroll
                for (int mi = 0; mi < 4; mi++) MMA16816(acc[mi][ni], ah[mi], bl);
            }
        }
        __syncthreads();
    }

    // ---------------- epilogue: stage C in smem, bulk-copy out --------------
    if (MODE == 0) {
        const uint32_t chi = sbase, clo = sbase + 32768;
        #pragma unroll
        for (int mi = 0; mi < 4; mi++) {
            #pragma unroll
            for (int ni = 0; ni < 4; ni++) {
                const int nl = wn + ni * 8 + 2 * (lane & 3);
                const int rl = wm + mi * 16 + (lane >> 2);
                float2 bv = *(const float2*)(bias + nb * 128 + nl);
                float v0 = acc[mi][ni][0] + bv.x;
                float v1 = acc[mi][ni][1] + bv.y;
                float v2 = acc[mi][ni][2] + bv.x;
                float v3 = acc[mi][ni][3] + bv.y;
                v0 = (v0 >= 0.0f) ? v0 : NEG_SLOPE * v0;
                v1 = (v1 >= 0.0f) ? v1 : NEG_SLOPE * v1;
                v2 = (v2 >= 0.0f) ? v2 : NEG_SLOPE * v2;
                v3 = (v3 >= 0.0f) ? v3 : NEG_SLOPE * v3;
                __half h0, l0, h1, l1, h2, l2, h3, l3;
                split_h(v0, h0, l0); split_h(v1, h1, l1);
                split_h(v2, h2, l2); split_h(v3, h3, l3);
                const uint32_t tb = (uint32_t)(nl >> 5) * 8192;
                const uint32_t off = swz((uint32_t)rl * 64 + (uint32_t)(nl & 31) * 2);
                asm volatile("st.shared.b32 [%0], %1;" :: "r"(chi + tb + off),       "r"(pack_h2(h0, h1)) : "memory");
                asm volatile("st.shared.b32 [%0], %1;" :: "r"(chi + tb + off + 512), "r"(pack_h2(h2, h3)) : "memory");
                asm volatile("st.shared.b32 [%0], %1;" :: "r"(clo + tb + off),       "r"(pack_h2(l0, l1)) : "memory");
                asm volatile("st.shared.b32 [%0], %1;" :: "r"(clo + tb + off + 512), "r"(pack_h2(l2, l3)) : "memory");
            }
        }
        __syncthreads();
        if (tid == 0) {
            asm volatile("fence.proxy.async;" ::: "memory");
            const size_t tbase = (size_t)mb * 32 + (size_t)nb * 4;
            #pragma unroll
            for (int t = 0; t < 4; t++) {
                bulk_s2g((char*)Ohi + (tbase + t) * 8192, chi + t * 8192, 8192);
                bulk_s2g((char*)Olo + (tbase + t) * 8192, clo + t * 8192, 8192);
            }
            asm volatile("cp.async.bulk.commit_group;" ::: "memory");
            asm volatile("cp.async.bulk.wait_group 0;" ::: "memory");
        }
    } else {
        // fp32 128x128 tile, row-major rows of 512B (64KB staging)
        const uint32_t cf = sbase;
        #pragma unroll
        for (int mi = 0; mi < 4; mi++) {
            #pragma unroll
            for (int ni = 0; ni < 4; ni++) {
                const int nl = wn + ni * 8 + 2 * (lane & 3);
                const int rl = wm + mi * 16 + (lane >> 2);
                float2 bv = *(const float2*)(bias + nb * 128 + nl);
                float2 p0 = make_float2(tanhf(acc[mi][ni][0] + bv.x),
                                        tanhf(acc[mi][ni][1] + bv.y));
                float2 p1 = make_float2(tanhf(acc[mi][ni][2] + bv.x),
                                        tanhf(acc[mi][ni][3] + bv.y));
                uint32_t a0 = cf + (uint32_t)rl * 512 + (uint32_t)nl * 4;
                asm volatile("st.shared.v2.f32 [%0], {%1, %2};"
                             :: "r"(a0), "f"(p0.x), "f"(p0.y) : "memory");
                asm volatile("st.shared.v2.f32 [%0], {%1, %2};"
                             :: "r"(a0 + 8 * 512), "f"(p1.x), "f"(p1.y) : "memory");
            }
        }
        __syncthreads();
        const uint32_t cf_off = cf - smem_u32(dsm);
        #pragma unroll
        for (int p = 0; p < 16; p++) {
            int idx = p * 256 + tid;
            int r = idx >> 5;
            int c4 = idx & 31;
            uint4 v = *(const uint4*)(dsm + cf_off + r * 512 + c4 * 16);
            *(uint4*)(Of + (size_t)(mb * 128 + r) * Ntot + nb * 128 + c4 * 4) = v;
        }
    }
}

// ---------------------------------------------------------------------------
// FK chain (validated)
// ---------------------------------------------------------------------------
__global__ __launch_bounds__(256) void fk_kernel(
    const float* __restrict__ joints, float* __restrict__ out)
{
    int row = blockIdx.x * blockDim.x + threadIdx.x;
    if (row >= BATCH) return;
    const float4* jq = (const float4*)(joints + (size_t)row * 256);
    float* o = out + (size_t)row * 192;

    float r00 = 1, r01 = 0, r02 = 0;
    float r10 = 0, r11 = 1, r12 = 0;
    float r20 = 0, r21 = 0, r22 = 1;
    float t0 = 0, t1 = 0, t2 = 0;

    #pragma unroll 4
    for (int j = 0; j < 64; j++) {
        float4 q = jq[j];
        float w = q.x, x = q.y, y = q.z, z = q.w;
        float s = 2.0f / (w * w + x * x + y * y + z * z);

        float R00 = 1.0f - s * (y * y + z * z);
        float R01 = s * (x * y - z * w);
        float R02 = s * (x * z + y * w);
        float R10 = s * (x * y + z * w);
        float R11 = 1.0f - s * (x * x + z * z);
        float R12 = s * (y * z - x * w);
        float R20 = s * (x * z - y * w);
        float R21 = s * (y * z + x * w);
        float R22 = 1.0f - s * (x * x + y * y);

        float n00 = r00 * R00 + r01 * R10 + r02 * R20;
        float n01 = r00 * R01 + r01 * R11 + r02 * R21;
        float n02 = r00 * R02 + r01 * R12 + r02 * R22;
        float n10 = r10 * R00 + r11 * R10 + r12 * R20;
        float n11 = r10 * R01 + r11 * R11 + r12 * R21;
        float n12 = r10 * R02 + r11 * R12 + r12 * R22;
        float n20 = r20 * R00 + r21 * R10 + r22 * R20;
        float n21 = r20 * R01 + r21 * R11 + r22 * R21;
        float n22 = r20 * R02 + r21 * R12 + r22 * R22;

        float nt0 = r00 * R01 + r01 * R11 + r02 * R21 + t0;
        float nt1 = r10 * R01 + r11 * R11 + r12 * R21 + t1;
        float nt2 = r20 * R01 + r21 * R11 + r22 * R21 + t2;

        r00 = n00; r01 = n01; r02 = n02;
        r10 = n10; r11 = n11; r12 = n12;
        r20 = n20; r21 = n21; r22 = n22;
        t0 = nt0; t1 = nt1; t2 = nt2;

        o[j * 3 + 0] = t0;
        o[j * 3 + 1] = t1;
        o[j * 3 + 2] = t2;
    }
}

// ---------------------------------------------------------------------------
// Launch
// ---------------------------------------------------------------------------
extern "C" void kernel_launch(void* const* d_in, const int* in_sizes, int n_in,
                              void* d_out, int out_size)
{
    const float* x  = (const float*)d_in[0];
    const float* W1 = (const float*)d_in[1];
    const float* b1 = (const float*)d_in[2];
    const float* W2 = (const float*)d_in[3];
    const float* b2 = (const float*)d_in[4];
    const float* W3 = (const float*)d_in[5];
    const float* b3 = (const float*)d_in[6];
    const float* W4 = (const float*)d_in[7];
    const float* b4 = (const float*)d_in[8];
    float* out = (float*)d_out;

    __half *a0h, *a0l, *a1h, *a1l, *w2h, *w2l, *w3h, *w3l, *w4h, *w4l;
    float* jnt;
    cudaGetSymbolAddress((void**)&a0h, g_a0h);
    cudaGetSymbolAddress((void**)&a0l, g_a0l);
    cudaGetSymbolAddress((void**)&a1h, g_a1h);
    cudaGetSymbolAddress((void**)&a1l, g_a1l);
    cudaGetSymbolAddress((void**)&w2h, g_w2h);
    cudaGetSymbolAddress((void**)&w2l, g_w2l);
    cudaGetSymbolAddress((void**)&w3h, g_w3h);
    cudaGetSymbolAddress((void**)&w3l, g_w3l);
    cudaGetSymbolAddress((void**)&w4h, g_w4h);
    cudaGetSymbolAddress((void**)&w4l, g_w4l);
    cudaGetSymbolAddress((void**)&jnt, g_joints);

    const int SMEM = 3 * 32768 + 1024;   // 99328 -> 2 CTAs/SM
    cudaFuncSetAttribute(gemm_kernel<0>, cudaFuncAttributeMaxDynamicSharedMemorySize, SMEM);
    cudaFuncSetAttribute(gemm_kernel<1>, cudaFuncAttributeMaxDynamicSharedMemorySize, SMEM);

    layer1_kernel<<<(BATCH * 128) / 256, 256>>>(x, W1, b1, a0h, a0l);
    wconv_kernel<<<(1024 * 128) / 256, 256>>>(W2, w2h, w2l, 1024);
    wconv_kernel<<<(1024 * 128) / 256, 256>>>(W3, w3h, w3l, 1024);
    wconv_kernel<<<(256 * 128) / 256, 256>>>(W4, w4h, w4l, 256);

    gemm_kernel<0><<<dim3(8, 128), 256, SMEM>>>(a0h, a0l, w2h, w2l, b2,
                                                a1h, a1l, nullptr, 1024);
    gemm_kernel<0><<<dim3(8, 128), 256, SMEM>>>(a1h, a1l, w3h, w3l, b3,
                                                a0h, a0l, nullptr, 1024);
    gemm_kernel<1><<<dim3(2, 128), 256, SMEM>>>(a0h, a0l, w4h, w4l, b4,
                                                nullptr, nullptr, jnt, 256);
    fk_kernel<<<BATCH / 256, 256>>>(jnt, out);
}